// round 7
// baseline (speedup 1.0000x reference)
#include <cuda_runtime.h>
#include <cstdint>

#define D 128
#define D4 32          // D / 4
#define N_MAX 50000
#define E_MAX 600000
#define NPB 32         // nodes per tile in the fused kernel
#define LN_EPS 1e-5f
#define SCAN_T 1024
#define FUSED_BLOCKS 296   // 2 per SM (148 SMs)

// Scratch (device globals; allocation-free per harness rules)
__device__ int g_deg[N_MAX];
__device__ int g_rowptr[N_MAX + 1];
__device__ int g_cursor[N_MAX];
__device__ int g_col[E_MAX];

// ---------------------------------------------------------------------------
// Kernel 0: deg = 0  (must run every launch; graph replays reuse memory)
// ---------------------------------------------------------------------------
__global__ void k_zero_deg(int N) {
    int i = blockIdx.x * blockDim.x + threadIdx.x;
    if (i < N) g_deg[i] = 0;
}

// ---------------------------------------------------------------------------
// Kernel 1: histogram of dst  (4 edges per thread via int4 for MLP)
// ---------------------------------------------------------------------------
__global__ void k_hist(const int4* __restrict__ dst4, int E4, 
                       const int* __restrict__ dst, int E) {
    int i = blockIdx.x * blockDim.x + threadIdx.x;
    if (i < E4) {
        int4 d = dst4[i];
        atomicAdd(&g_deg[d.x], 1);
        atomicAdd(&g_deg[d.y], 1);
        atomicAdd(&g_deg[d.z], 1);
        atomicAdd(&g_deg[d.w], 1);
    } else if (i == E4) {          // tail (E % 4 edges), single thread
        for (int e = E4 * 4; e < E; e++) atomicAdd(&g_deg[dst[e]], 1);
    }
}

// ---------------------------------------------------------------------------
// Kernel 2: exclusive prefix scan over deg -> row_ptr, cursor  (single block)
// ---------------------------------------------------------------------------
__global__ __launch_bounds__(SCAN_T)
void k_scan(int N) {
    __shared__ int part[SCAN_T];
    const int t = threadIdx.x;
    const int per = (N + SCAN_T - 1) / SCAN_T;
    const int begin = t * per;
    int end = begin + per; if (end > N) end = N;

    int s = 0;
    for (int i = begin; i < end; i++) s += g_deg[i];
    part[t] = s;
    __syncthreads();

    for (int off = 1; off < SCAN_T; off <<= 1) {
        int v = (t >= off) ? part[t - off] : 0;
        __syncthreads();
        part[t] += v;
        __syncthreads();
    }

    int run = part[t] - s;    // exclusive base for this thread's chunk
    for (int i = begin; i < end; i++) {
        g_rowptr[i] = run;
        g_cursor[i] = run;
        run += g_deg[i];      // second read hits L1
    }
    if (t == SCAN_T - 1) g_rowptr[N] = part[SCAN_T - 1];
}

// ---------------------------------------------------------------------------
// Kernel 3: bucket fill  col[cursor[dst[e]]++] = src[e]
// 4 edges per thread via int4 loads (MLP on the atomic+store chain).
// ---------------------------------------------------------------------------
__global__ void k_fill(const int4* __restrict__ src4,
                       const int4* __restrict__ dst4, int E4,
                       const int* __restrict__ src,
                       const int* __restrict__ dst, int E) {
    int i = blockIdx.x * blockDim.x + threadIdx.x;
    if (i < E4) {
        int4 s = src4[i];
        int4 d = dst4[i];
        int p0 = atomicAdd(&g_cursor[d.x], 1);
        int p1 = atomicAdd(&g_cursor[d.y], 1);
        int p2 = atomicAdd(&g_cursor[d.z], 1);
        int p3 = atomicAdd(&g_cursor[d.w], 1);
        g_col[p0] = s.x;
        g_col[p1] = s.y;
        g_col[p2] = s.z;
        g_col[p3] = s.w;
    } else if (i == E4) {          // tail
        for (int e = E4 * 4; e < E; e++) {
            int p = atomicAdd(&g_cursor[dst[e]], 1);
            g_col[p] = src[e];
        }
    }
}

// ---------------------------------------------------------------------------
// Kernel 4: FUSED  gather -> GEMM -> LayerNorm -> ReLU
// Persistent blocks, 128 threads, 2/SM. Per tile of 32 nodes:
//   Phase A (gather): warp per node; acc = h[node] + sum h[col[j]] -> xs
//   Phase B (gemm):   thread j owns column j; W row j in 128 regs; FFMA2
//   Phase C (LN):     warp per node; shuffle reduce; float4 stores
// Gather (L2-bound) of one block overlaps FFMA of the co-resident block.
// ---------------------------------------------------------------------------
__global__ __launch_bounds__(128, 2)
void k_fused(const float4* __restrict__ h4,
             const float* __restrict__ W,
             const float* __restrict__ bias,
             const float* __restrict__ gamma,
             const float* __restrict__ beta,
             float* __restrict__ out,
             int N) {
    __shared__ float4 xs[NPB][D4];     // gathered tile
    __shared__ float  ys[NPB][D];      // pre-LN outputs

    const int j    = threadIdx.x;      // output column 0..127
    const int lane = j & 31;
    const int warp = j >> 5;

    // W row j as 32 x ulonglong2 (each .x/.y is a packed f32x2)
    ulonglong2 w[D4];
    const ulonglong2* W2 = reinterpret_cast<const ulonglong2*>(W);
#pragma unroll
    for (int k = 0; k < D4; k++) w[k] = W2[j * D4 + k];

    const float bj = bias[j];
    const float4 g4  = reinterpret_cast<const float4*>(gamma)[lane];
    const float4 be4 = reinterpret_cast<const float4*>(beta)[lane];

    const int numTiles = (N + NPB - 1) / NPB;
    for (int tile = blockIdx.x; tile < numTiles; tile += gridDim.x) {
        const int base = tile * NPB;
        int valid = N - base; if (valid > NPB) valid = NPB;

        // ---- Phase A: gather aggregate directly into shared ----
        for (int n = warp; n < NPB; n += 4) {
            int node = base + n;
            float4 acc = make_float4(0.f, 0.f, 0.f, 0.f);
            if (node < N) {
                acc = h4[(size_t)node * D4 + lane];      // residual
                int jj  = g_rowptr[node];
                int end = g_rowptr[node + 1];
                for (; jj + 3 < end; jj += 4) {
                    int s0 = g_col[jj],     s1 = g_col[jj + 1];
                    int s2 = g_col[jj + 2], s3 = g_col[jj + 3];
                    float4 v0 = h4[(size_t)s0 * D4 + lane];
                    float4 v1 = h4[(size_t)s1 * D4 + lane];
                    float4 v2 = h4[(size_t)s2 * D4 + lane];
                    float4 v3 = h4[(size_t)s3 * D4 + lane];
                    acc.x += (v0.x + v1.x) + (v2.x + v3.x);
                    acc.y += (v0.y + v1.y) + (v2.y + v3.y);
                    acc.z += (v0.z + v1.z) + (v2.z + v3.z);
                    acc.w += (v0.w + v1.w) + (v2.w + v3.w);
                }
                for (; jj < end; jj++) {
                    float4 v0 = h4[(size_t)g_col[jj] * D4 + lane];
                    acc.x += v0.x; acc.y += v0.y; acc.z += v0.z; acc.w += v0.w;
                }
            }
            xs[n][lane] = acc;
        }
        __syncthreads();

        // ---- Phase B: y = xs @ W^T + b  (FFMA2, 4 packed chains) ----
        for (int n = 0; n < NPB; n++) {
            unsigned long long a01a = 0ull, a23a = 0ull, a01b = 0ull, a23b = 0ull;
            const ulonglong2* xrow = reinterpret_cast<const ulonglong2*>(xs[n]);
#pragma unroll
            for (int k = 0; k < D4; k += 2) {
                ulonglong2 x0 = xrow[k];
                ulonglong2 x1 = xrow[k + 1];
                asm("fma.rn.f32x2 %0, %1, %2, %0;" : "+l"(a01a) : "l"(x0.x), "l"(w[k].x));
                asm("fma.rn.f32x2 %0, %1, %2, %0;" : "+l"(a23a) : "l"(x0.y), "l"(w[k].y));
                asm("fma.rn.f32x2 %0, %1, %2, %0;" : "+l"(a01b) : "l"(x1.x), "l"(w[k + 1].x));
                asm("fma.rn.f32x2 %0, %1, %2, %0;" : "+l"(a23b) : "l"(x1.y), "l"(w[k + 1].y));
            }
            unsigned int l0, h0, l1, h1, l2, h2, l3, h3;
            asm("mov.b64 {%0, %1}, %2;" : "=r"(l0), "=r"(h0) : "l"(a01a));
            asm("mov.b64 {%0, %1}, %2;" : "=r"(l1), "=r"(h1) : "l"(a23a));
            asm("mov.b64 {%0, %1}, %2;" : "=r"(l2), "=r"(h2) : "l"(a01b));
            asm("mov.b64 {%0, %1}, %2;" : "=r"(l3), "=r"(h3) : "l"(a23b));
            float y = ((__uint_as_float(l0) + __uint_as_float(h0)) +
                       (__uint_as_float(l1) + __uint_as_float(h1))) +
                      ((__uint_as_float(l2) + __uint_as_float(h2)) +
                       (__uint_as_float(l3) + __uint_as_float(h3))) + bj;
            ys[n][j] = y;
        }
        __syncthreads();

        // ---- Phase C: LN + ReLU, warp per node ----
        for (int n = warp; n < valid; n += 4) {
            float4 v = reinterpret_cast<const float4*>(ys[n])[lane];
            float s = (v.x + v.y) + (v.z + v.w);
            float q = (v.x * v.x + v.y * v.y) + (v.z * v.z + v.w * v.w);
#pragma unroll
            for (int o = 16; o > 0; o >>= 1) {
                s += __shfl_xor_sync(0xFFFFFFFFu, s, o);
                q += __shfl_xor_sync(0xFFFFFFFFu, q, o);
            }
            float mu  = s * (1.0f / D);
            float var = q * (1.0f / D) - mu * mu;
            float rs  = rsqrtf(var + LN_EPS);
            float4 o4;
            o4.x = fmaxf((v.x - mu) * rs * g4.x + be4.x, 0.f);
            o4.y = fmaxf((v.y - mu) * rs * g4.y + be4.y, 0.f);
            o4.z = fmaxf((v.z - mu) * rs * g4.z + be4.z, 0.f);
            o4.w = fmaxf((v.w - mu) * rs * g4.w + be4.w, 0.f);
            reinterpret_cast<float4*>(out + (size_t)(base + n) * D)[lane] = o4;
        }
        __syncthreads();   // xs/ys reused next tile
    }
}

// ---------------------------------------------------------------------------
extern "C" void kernel_launch(void* const* d_in, const int* in_sizes, int n_in,
                              void* d_out, int out_size) {
    const float* h     = (const float*)d_in[0];
    const int*   ei    = (const int*)d_in[1];   // [2, E] int32
    const float* W     = (const float*)d_in[2];
    const float* bias  = (const float*)d_in[3];
    const float* gamma = (const float*)d_in[4];
    const float* beta  = (const float*)d_in[5];
    float*       out   = (float*)d_out;

    const int N = in_sizes[0] / D;
    const int E = in_sizes[1] / 2;
    const int* src = ei;
    const int* dst = ei + E;
    const int E4 = E / 4;   // dst = ei + E; E even, and E%4==0 for 600000

    k_zero_deg<<<(N + 255) / 256, 256>>>(N);
    k_hist<<<(E4 + 256) / 256, 256>>>(reinterpret_cast<const int4*>(dst), E4, dst, E);
    k_scan<<<1, SCAN_T>>>(N);
    k_fill<<<(E4 + 256) / 256, 256>>>(reinterpret_cast<const int4*>(src),
                                      reinterpret_cast<const int4*>(dst), E4,
                                      src, dst, E);
    k_fused<<<FUSED_BLOCKS, 128>>>(reinterpret_cast<const float4*>(h),
                                   W, bias, gamma, beta, out, N);
}

// round 8
// speedup vs baseline: 1.1905x; 1.1905x over previous
#include <cuda_runtime.h>
#include <cstdint>

#define D 128
#define D4 32          // D / 4
#define N_MAX 50000
#define E_MAX 600000
#define NPB 32         // nodes per tile in the GEMM kernel
#define LN_EPS 1e-5f
#define SCAN_T 1024
#define GEMM_BLOCKS 296   // 2 per SM (148 SMs)

// Scratch (device globals; allocation-free per harness rules)
__device__ float g_agg[(size_t)N_MAX * D];
__device__ int   g_deg[N_MAX];
__device__ int   g_rowptr[N_MAX + 1];
__device__ int   g_cursor[N_MAX];
__device__ int   g_col[E_MAX];

// ---------------------------------------------------------------------------
// Kernel 0: deg = 0  (must run every launch; graph replays reuse memory)
// ---------------------------------------------------------------------------
__global__ void k_zero_deg(int N) {
    int i = blockIdx.x * blockDim.x + threadIdx.x;
    if (i < N) g_deg[i] = 0;
}

// ---------------------------------------------------------------------------
// Kernel 1: histogram of dst  (8 edges per thread via 2x int4 for MLP)
// ---------------------------------------------------------------------------
__global__ void k_hist(const int4* __restrict__ dst4, int E8,
                       const int* __restrict__ dst, int E) {
    int i = blockIdx.x * blockDim.x + threadIdx.x;
    if (i < E8) {
        int4 d0 = dst4[2 * i];
        int4 d1 = dst4[2 * i + 1];
        atomicAdd(&g_deg[d0.x], 1);
        atomicAdd(&g_deg[d0.y], 1);
        atomicAdd(&g_deg[d0.z], 1);
        atomicAdd(&g_deg[d0.w], 1);
        atomicAdd(&g_deg[d1.x], 1);
        atomicAdd(&g_deg[d1.y], 1);
        atomicAdd(&g_deg[d1.z], 1);
        atomicAdd(&g_deg[d1.w], 1);
    } else if (i == E8) {          // tail (E % 8 edges), single thread
        for (int e = E8 * 8; e < E; e++) atomicAdd(&g_deg[dst[e]], 1);
    }
}

// ---------------------------------------------------------------------------
// Kernel 2: exclusive prefix scan over deg -> row_ptr, cursor  (single block)
// ---------------------------------------------------------------------------
__global__ __launch_bounds__(SCAN_T)
void k_scan(int N) {
    __shared__ int part[SCAN_T];
    const int t = threadIdx.x;
    const int per = (N + SCAN_T - 1) / SCAN_T;
    const int begin = t * per;
    int end = begin + per; if (end > N) end = N;

    int s = 0;
    for (int i = begin; i < end; i++) s += g_deg[i];
    part[t] = s;
    __syncthreads();

    for (int off = 1; off < SCAN_T; off <<= 1) {
        int v = (t >= off) ? part[t - off] : 0;
        __syncthreads();
        part[t] += v;
        __syncthreads();
    }

    int run = part[t] - s;    // exclusive base for this thread's chunk
    for (int i = begin; i < end; i++) {
        g_rowptr[i] = run;
        g_cursor[i] = run;
        run += g_deg[i];      // second read hits L1
    }
    if (t == SCAN_T - 1) g_rowptr[N] = part[SCAN_T - 1];
}

// ---------------------------------------------------------------------------
// Kernel 3: bucket fill  col[cursor[dst[e]]++] = src[e]
// 8 edges per thread (2x int4) for 8 independent atomic+store chains.
// ---------------------------------------------------------------------------
__global__ void k_fill(const int4* __restrict__ src4,
                       const int4* __restrict__ dst4, int E8,
                       const int* __restrict__ src,
                       const int* __restrict__ dst, int E) {
    int i = blockIdx.x * blockDim.x + threadIdx.x;
    if (i < E8) {
        int4 s0 = src4[2 * i],     s1 = src4[2 * i + 1];
        int4 d0 = dst4[2 * i],     d1 = dst4[2 * i + 1];
        int p0 = atomicAdd(&g_cursor[d0.x], 1);
        int p1 = atomicAdd(&g_cursor[d0.y], 1);
        int p2 = atomicAdd(&g_cursor[d0.z], 1);
        int p3 = atomicAdd(&g_cursor[d0.w], 1);
        int p4 = atomicAdd(&g_cursor[d1.x], 1);
        int p5 = atomicAdd(&g_cursor[d1.y], 1);
        int p6 = atomicAdd(&g_cursor[d1.z], 1);
        int p7 = atomicAdd(&g_cursor[d1.w], 1);
        g_col[p0] = s0.x;
        g_col[p1] = s0.y;
        g_col[p2] = s0.z;
        g_col[p3] = s0.w;
        g_col[p4] = s1.x;
        g_col[p5] = s1.y;
        g_col[p6] = s1.z;
        g_col[p7] = s1.w;
    } else if (i == E8) {          // tail
        for (int e = E8 * 8; e < E; e++) {
            int p = atomicAdd(&g_cursor[dst[e]], 1);
            g_col[p] = src[e];
        }
    }
}

// ---------------------------------------------------------------------------
// Kernel 4: gather-aggregate  agg[n] = h[n] + sum_{j in row n} h[col[j]]
// One warp per node; lane owns float4 columns [4l, 4l+4). Unroll 8 for MLP.
// ---------------------------------------------------------------------------
__global__ __launch_bounds__(512)
void k_gather(const float4* __restrict__ h4, int N) {
    int wid  = (blockIdx.x * blockDim.x + threadIdx.x) >> 5;
    int lane = threadIdx.x & 31;
    if (wid >= N) return;

    int start = g_rowptr[wid];
    int end   = g_rowptr[wid + 1];

    float4 acc = h4[(size_t)wid * D4 + lane];   // residual

    int j = start;
    for (; j + 7 < end; j += 8) {
        int s0 = g_col[j],     s1 = g_col[j + 1];
        int s2 = g_col[j + 2], s3 = g_col[j + 3];
        int s4 = g_col[j + 4], s5 = g_col[j + 5];
        int s6 = g_col[j + 6], s7 = g_col[j + 7];
        float4 v0 = h4[(size_t)s0 * D4 + lane];
        float4 v1 = h4[(size_t)s1 * D4 + lane];
        float4 v2 = h4[(size_t)s2 * D4 + lane];
        float4 v3 = h4[(size_t)s3 * D4 + lane];
        float4 v4 = h4[(size_t)s4 * D4 + lane];
        float4 v5 = h4[(size_t)s5 * D4 + lane];
        float4 v6 = h4[(size_t)s6 * D4 + lane];
        float4 v7 = h4[(size_t)s7 * D4 + lane];
        acc.x += ((v0.x + v1.x) + (v2.x + v3.x)) + ((v4.x + v5.x) + (v6.x + v7.x));
        acc.y += ((v0.y + v1.y) + (v2.y + v3.y)) + ((v4.y + v5.y) + (v6.y + v7.y));
        acc.z += ((v0.z + v1.z) + (v2.z + v3.z)) + ((v4.z + v5.z) + (v6.z + v7.z));
        acc.w += ((v0.w + v1.w) + (v2.w + v3.w)) + ((v4.w + v5.w) + (v6.w + v7.w));
    }
    for (; j + 3 < end; j += 4) {
        int s0 = g_col[j],     s1 = g_col[j + 1];
        int s2 = g_col[j + 2], s3 = g_col[j + 3];
        float4 v0 = h4[(size_t)s0 * D4 + lane];
        float4 v1 = h4[(size_t)s1 * D4 + lane];
        float4 v2 = h4[(size_t)s2 * D4 + lane];
        float4 v3 = h4[(size_t)s3 * D4 + lane];
        acc.x += (v0.x + v1.x) + (v2.x + v3.x);
        acc.y += (v0.y + v1.y) + (v2.y + v3.y);
        acc.z += (v0.z + v1.z) + (v2.z + v3.z);
        acc.w += (v0.w + v1.w) + (v2.w + v3.w);
    }
    for (; j < end; j++) {
        float4 v0 = h4[(size_t)g_col[j] * D4 + lane];
        acc.x += v0.x; acc.y += v0.y; acc.z += v0.z; acc.w += v0.w;
    }

    reinterpret_cast<float4*>(g_agg)[(size_t)wid * D4 + lane] = acc;
}

// ---------------------------------------------------------------------------
// Kernel 5: fused  y = agg @ W^T + b ; LayerNorm ; ReLU
// Persistent blocks. Thread j owns output column j; W row j in 128 regs as
// packed f32x2 pairs. Inner loop uses fma.rn.f32x2 (FFMA2 — 2 MACs/instr).
// LN done batched after the whole tile: warp-per-node shuffle reduce.
// ---------------------------------------------------------------------------
__global__ __launch_bounds__(128, 2)
void k_gemm_ln_relu(const float* __restrict__ W,
                    const float* __restrict__ bias,
                    const float* __restrict__ gamma,
                    const float* __restrict__ beta,
                    float* __restrict__ out,
                    int N) {
    __shared__ float4 xs[NPB][D4];     // input tile
    __shared__ float  ys[NPB][D];      // pre-LN outputs

    const int j    = threadIdx.x;      // output column 0..127
    const int lane = j & 31;
    const int warp = j >> 5;

    // W row j as 32 x ulonglong2 (each .x/.y is a packed f32x2)
    ulonglong2 w[D4];
    const ulonglong2* W2 = reinterpret_cast<const ulonglong2*>(W);
#pragma unroll
    for (int k = 0; k < D4; k++) w[k] = W2[j * D4 + k];

    const float bj = bias[j];
    const float4 g4  = reinterpret_cast<const float4*>(gamma)[lane];
    const float4 be4 = reinterpret_cast<const float4*>(beta)[lane];

    const int numTiles = (N + NPB - 1) / NPB;
    for (int tile = blockIdx.x; tile < numTiles; tile += gridDim.x) {
        const int base  = tile * NPB;
        int valid = N - base; if (valid > NPB) valid = NPB;

        // Stage tile into shared
        const float4* X4 = reinterpret_cast<const float4*>(g_agg) + (size_t)base * D4;
        for (int i = j; i < NPB * D4; i += 128) {
            int r = i >> 5;
            xs[r][i & 31] = (r < valid) ? X4[i] : make_float4(0.f, 0.f, 0.f, 0.f);
        }
        __syncthreads();

        // Compute y for every node in the tile (no syncs inside)
        for (int n = 0; n < NPB; n++) {
            unsigned long long a01a = 0ull, a23a = 0ull, a01b = 0ull, a23b = 0ull;
            const ulonglong2* xrow = reinterpret_cast<const ulonglong2*>(xs[n]);
#pragma unroll
            for (int k = 0; k < D4; k += 2) {
                ulonglong2 x0 = xrow[k];
                ulonglong2 x1 = xrow[k + 1];
                asm("fma.rn.f32x2 %0, %1, %2, %0;" : "+l"(a01a) : "l"(x0.x), "l"(w[k].x));
                asm("fma.rn.f32x2 %0, %1, %2, %0;" : "+l"(a23a) : "l"(x0.y), "l"(w[k].y));
                asm("fma.rn.f32x2 %0, %1, %2, %0;" : "+l"(a01b) : "l"(x1.x), "l"(w[k + 1].x));
                asm("fma.rn.f32x2 %0, %1, %2, %0;" : "+l"(a23b) : "l"(x1.y), "l"(w[k + 1].y));
            }
            unsigned int l0, h0, l1, h1, l2, h2, l3, h3;
            asm("mov.b64 {%0, %1}, %2;" : "=r"(l0), "=r"(h0) : "l"(a01a));
            asm("mov.b64 {%0, %1}, %2;" : "=r"(l1), "=r"(h1) : "l"(a23a));
            asm("mov.b64 {%0, %1}, %2;" : "=r"(l2), "=r"(h2) : "l"(a01b));
            asm("mov.b64 {%0, %1}, %2;" : "=r"(l3), "=r"(h3) : "l"(a23b));
            float y = ((__uint_as_float(l0) + __uint_as_float(h0)) +
                       (__uint_as_float(l1) + __uint_as_float(h1))) +
                      ((__uint_as_float(l2) + __uint_as_float(h2)) +
                       (__uint_as_float(l3) + __uint_as_float(h3))) + bj;
            ys[n][j] = y;
        }
        __syncthreads();

        // Batched LN + ReLU: warp handles nodes warp, warp+4, ...
        for (int n = warp; n < valid; n += 4) {
            float4 v = reinterpret_cast<const float4*>(ys[n])[lane];
            float s = (v.x + v.y) + (v.z + v.w);
            float q = (v.x * v.x + v.y * v.y) + (v.z * v.z + v.w * v.w);
#pragma unroll
            for (int o = 16; o > 0; o >>= 1) {
                s += __shfl_xor_sync(0xFFFFFFFFu, s, o);
                q += __shfl_xor_sync(0xFFFFFFFFu, q, o);
            }
            float mu  = s * (1.0f / D);
            float var = q * (1.0f / D) - mu * mu;
            float rs  = rsqrtf(var + LN_EPS);
            float4 o4;
            o4.x = fmaxf((v.x - mu) * rs * g4.x + be4.x, 0.f);
            o4.y = fmaxf((v.y - mu) * rs * g4.y + be4.y, 0.f);
            o4.z = fmaxf((v.z - mu) * rs * g4.z + be4.z, 0.f);
            o4.w = fmaxf((v.w - mu) * rs * g4.w + be4.w, 0.f);
            reinterpret_cast<float4*>(out + (size_t)(base + n) * D)[lane] = o4;
        }
        __syncthreads();   // xs/ys reused next tile
    }
}

// ---------------------------------------------------------------------------
extern "C" void kernel_launch(void* const* d_in, const int* in_sizes, int n_in,
                              void* d_out, int out_size) {
    const float* h     = (const float*)d_in[0];
    const int*   ei    = (const int*)d_in[1];   // [2, E] int32
    const float* W     = (const float*)d_in[2];
    const float* bias  = (const float*)d_in[3];
    const float* gamma = (const float*)d_in[4];
    const float* beta  = (const float*)d_in[5];
    float*       out   = (float*)d_out;

    const int N = in_sizes[0] / D;
    const int E = in_sizes[1] / 2;
    const int* src = ei;
    const int* dst = ei + E;
    const int E8 = E / 8;

    k_zero_deg<<<(N + 255) / 256, 256>>>(N);
    k_hist<<<(E8 + 256) / 256, 256>>>(reinterpret_cast<const int4*>(dst), E8, dst, E);
    k_scan<<<1, SCAN_T>>>(N);
    k_fill<<<(E8 + 256) / 256, 256>>>(reinterpret_cast<const int4*>(src),
                                      reinterpret_cast<const int4*>(dst), E8,
                                      src, dst, E);
    k_gather<<<(N * 32 + 511) / 512, 512>>>(reinterpret_cast<const float4*>(h), N);
    k_gemm_ln_relu<<<GEMM_BLOCKS, 128>>>(W, bias, gamma, beta, out, N);
}

// round 9
// speedup vs baseline: 1.6186x; 1.3597x over previous
#include <cuda_runtime.h>
#include <cstdint>

#define D 128
#define D4 32          // D / 4
#define N_MAX 50000
#define NPB 32         // nodes per tile in the GEMM kernel
#define LN_EPS 1e-5f
#define GEMM_BLOCKS 296   // 2 per SM (148 SMs)

// Scratch: aggregated features (agg = h + sum_{e: dst=n} h[src])
__device__ float g_agg[(size_t)N_MAX * D];

// ---------------------------------------------------------------------------
// Kernel 1: agg = h  (residual pre-load; scatter accumulates on top)
// ---------------------------------------------------------------------------
__global__ void k_init_agg(const float4* __restrict__ h4, int n4) {
    int i = blockIdx.x * blockDim.x + threadIdx.x;
    float4* agg4 = reinterpret_cast<float4*>(g_agg);
    if (i < n4) agg4[i] = h4[i];
}

// ---------------------------------------------------------------------------
// Kernel 2: scatter-add  agg[dst[e]] += h[src[e]]   (one warp per edge)
// Each lane owns one float4 (16B) of the 512B row and issues a SINGLE
// vectorized reduction: red.global.add.v4.f32  ->  REDG.128.ADD.
// 4x fewer L2 atomic-ALU ops than scalar atomicAdd.
// ---------------------------------------------------------------------------
__global__ __launch_bounds__(256)
void k_scatter_v4(const float4* __restrict__ h4,
                  const int* __restrict__ src,
                  const int* __restrict__ dst,
                  int E) {
    int warp_id = (blockIdx.x * blockDim.x + threadIdx.x) >> 5;
    int lane = threadIdx.x & 31;
    if (warp_id >= E) return;
    int s = src[warp_id];          // warp-uniform load (broadcast)
    int d = dst[warp_id];
    float4 v = h4[(size_t)s * D4 + lane];
    float4* ap = reinterpret_cast<float4*>(g_agg) + (size_t)d * D4 + lane;
    asm volatile("red.global.add.v4.f32 [%0], {%1, %2, %3, %4};"
                 :: "l"(ap), "f"(v.x), "f"(v.y), "f"(v.z), "f"(v.w)
                 : "memory");
}

// ---------------------------------------------------------------------------
// Kernel 3: fused  y = agg @ W^T + b ; LayerNorm ; ReLU
// Persistent blocks. Thread j owns output column j; W row j in 128 regs as
// packed f32x2 pairs. Inner loop uses fma.rn.f32x2 (FFMA2 — 2 MACs/instr).
// LN done batched after the whole tile: warp-per-node shuffle reduce.
// ---------------------------------------------------------------------------
__global__ __launch_bounds__(128, 2)
void k_gemm_ln_relu(const float* __restrict__ W,
                    const float* __restrict__ bias,
                    const float* __restrict__ gamma,
                    const float* __restrict__ beta,
                    float* __restrict__ out,
                    int N) {
    __shared__ float4 xs[NPB][D4];     // input tile
    __shared__ float  ys[NPB][D];      // pre-LN outputs

    const int j    = threadIdx.x;      // output column 0..127
    const int lane = j & 31;
    const int warp = j >> 5;

    // W row j as 32 x ulonglong2 (each .x/.y is a packed f32x2)
    ulonglong2 w[D4];
    const ulonglong2* W2 = reinterpret_cast<const ulonglong2*>(W);
#pragma unroll
    for (int k = 0; k < D4; k++) w[k] = W2[j * D4 + k];

    const float bj = bias[j];
    const float4 g4  = reinterpret_cast<const float4*>(gamma)[lane];
    const float4 be4 = reinterpret_cast<const float4*>(beta)[lane];

    const int numTiles = (N + NPB - 1) / NPB;
    for (int tile = blockIdx.x; tile < numTiles; tile += gridDim.x) {
        const int base  = tile * NPB;
        int valid = N - base; if (valid > NPB) valid = NPB;

        // Stage tile into shared
        const float4* X4 = reinterpret_cast<const float4*>(g_agg) + (size_t)base * D4;
        for (int i = j; i < NPB * D4; i += 128) {
            int r = i >> 5;
            xs[r][i & 31] = (r < valid) ? X4[i] : make_float4(0.f, 0.f, 0.f, 0.f);
        }
        __syncthreads();

        // Compute y for every node in the tile (no syncs inside)
        for (int n = 0; n < NPB; n++) {
            unsigned long long a01a = 0ull, a23a = 0ull, a01b = 0ull, a23b = 0ull;
            const ulonglong2* xrow = reinterpret_cast<const ulonglong2*>(xs[n]);
#pragma unroll
            for (int k = 0; k < D4; k += 2) {
                ulonglong2 x0 = xrow[k];
                ulonglong2 x1 = xrow[k + 1];
                asm("fma.rn.f32x2 %0, %1, %2, %0;" : "+l"(a01a) : "l"(x0.x), "l"(w[k].x));
                asm("fma.rn.f32x2 %0, %1, %2, %0;" : "+l"(a23a) : "l"(x0.y), "l"(w[k].y));
                asm("fma.rn.f32x2 %0, %1, %2, %0;" : "+l"(a01b) : "l"(x1.x), "l"(w[k + 1].x));
                asm("fma.rn.f32x2 %0, %1, %2, %0;" : "+l"(a23b) : "l"(x1.y), "l"(w[k + 1].y));
            }
            unsigned int l0, h0, l1, h1, l2, h2, l3, h3;
            asm("mov.b64 {%0, %1}, %2;" : "=r"(l0), "=r"(h0) : "l"(a01a));
            asm("mov.b64 {%0, %1}, %2;" : "=r"(l1), "=r"(h1) : "l"(a23a));
            asm("mov.b64 {%0, %1}, %2;" : "=r"(l2), "=r"(h2) : "l"(a01b));
            asm("mov.b64 {%0, %1}, %2;" : "=r"(l3), "=r"(h3) : "l"(a23b));
            float y = ((__uint_as_float(l0) + __uint_as_float(h0)) +
                       (__uint_as_float(l1) + __uint_as_float(h1))) +
                      ((__uint_as_float(l2) + __uint_as_float(h2)) +
                       (__uint_as_float(l3) + __uint_as_float(h3))) + bj;
            ys[n][j] = y;
        }
        __syncthreads();

        // Batched LN + ReLU: warp handles nodes warp, warp+4, ...
        for (int n = warp; n < valid; n += 4) {
            float4 v = reinterpret_cast<const float4*>(ys[n])[lane];
            float s = (v.x + v.y) + (v.z + v.w);
            float q = (v.x * v.x + v.y * v.y) + (v.z * v.z + v.w * v.w);
#pragma unroll
            for (int o = 16; o > 0; o >>= 1) {
                s += __shfl_xor_sync(0xFFFFFFFFu, s, o);
                q += __shfl_xor_sync(0xFFFFFFFFu, q, o);
            }
            float mu  = s * (1.0f / D);
            float var = q * (1.0f / D) - mu * mu;
            float rs  = rsqrtf(var + LN_EPS);
            float4 o4;
            o4.x = fmaxf((v.x - mu) * rs * g4.x + be4.x, 0.f);
            o4.y = fmaxf((v.y - mu) * rs * g4.y + be4.y, 0.f);
            o4.z = fmaxf((v.z - mu) * rs * g4.z + be4.z, 0.f);
            o4.w = fmaxf((v.w - mu) * rs * g4.w + be4.w, 0.f);
            reinterpret_cast<float4*>(out + (size_t)(base + n) * D)[lane] = o4;
        }
        __syncthreads();   // xs/ys reused next tile
    }
}

// ---------------------------------------------------------------------------
extern "C" void kernel_launch(void* const* d_in, const int* in_sizes, int n_in,
                              void* d_out, int out_size) {
    const float* h     = (const float*)d_in[0];
    const int*   ei    = (const int*)d_in[1];   // [2, E] int32
    const float* W     = (const float*)d_in[2];
    const float* bias  = (const float*)d_in[3];
    const float* gamma = (const float*)d_in[4];
    const float* beta  = (const float*)d_in[5];
    float*       out   = (float*)d_out;

    const int N = in_sizes[0] / D;
    const int E = in_sizes[1] / 2;
    const int* src = ei;
    const int* dst = ei + E;

    // 1) agg = h
    int n4 = N * D4;
    k_init_agg<<<(n4 + 255) / 256, 256>>>(reinterpret_cast<const float4*>(h), n4);

    // 2) vectorized scatter-add: 1 warp per edge, 8 edges per 256-thread block
    int blocks_sc = (E + 7) / 8;
    k_scatter_v4<<<blocks_sc, 256>>>(reinterpret_cast<const float4*>(h), src, dst, E);

    // 3) fused linear + layernorm + relu
    k_gemm_ln_relu<<<GEMM_BLOCKS, 128>>>(W, bias, gamma, beta, out, N);
}